// round 11
// baseline (speedup 1.0000x reference)
#include <cuda_runtime.h>
#include <cuda_fp16.h>
#include <math.h>

#define N_LEVELS   16
#define LOG2_T     19
#define TABLE_SIZE (1 << LOG2_T)
#define HASH_MASK  (TABLE_SIZE - 1)

#define PRIME_Y 2654435761u
#define PRIME_Z 805459861u

#define EMB_SCALE   8192.0f
#define EMB_UNSCALE (1.0f / 8192.0f)

// One 16B quad = corners (x,y),(x+1,y),(x,y+1),(x+1,y+1) at one z, fp16x2 each.
struct __align__(16) HQuad { __half2 c00, c10, c01, c11; };

// ---- smem levels 0-3 (quads)
#define N_SM 4
__device__ __constant__ int s_dims[N_SM] = {10, 12, 15, 18};
__device__ __constant__ int s_cmin[N_SM] = { 8, 10, 12, 16};
__device__ __constant__ int s_offc[N_SM] = {0, 1000, 2728, 6103};
#define S_TOTAL 11935          // 10^3+12^3+15^3+18^3 -> 190,960 B smem

// ---- gmem dense levels 4-11 (quads), +-1 margin windows
#define N_GD 8
__device__ __constant__ int g_dims[N_GD] = {24, 28, 36, 44, 55, 68, 84, 106};
__device__ __constant__ int g_cmin[N_GD] = {19, 24, 30, 39, 49, 62, 79, 100};
__device__ __constant__ int g_offc[N_GD] =
    {0, 13824, 35776, 82432, 167616, 333991, 648423, 1241127};
#define G_TOTAL 2432143        // sum of g_dims^3 -> ~38.9 MB

__device__ HQuad g_squad[S_TOTAL];
__device__ HQuad g_gquad[G_TOTAL];

struct LevelParams {
    float g[N_LEVELS];
    float rinv[N_LEVELS];
};

__device__ __forceinline__ unsigned int hash3(unsigned int cx, unsigned int cy,
                                              unsigned int cz)
{
    return (cx ^ (cy * PRIME_Y) ^ (cz * PRIME_Z)) & HASH_MASK;
}

// ---------------------------------------------------------------------------
// Repack kernels: build fp16 quad arrays (scaled by 2^13).
// ---------------------------------------------------------------------------
__device__ __forceinline__ HQuad make_quad(const float2* __restrict__ tab,
                                           int cmin, int d,
                                           int lx, int ly, int lz)
{
    int lx1 = min(lx + 1, d - 1);          // clamped entries are never consumed
    int ly1 = min(ly + 1, d - 1);
    unsigned int cx0 = (unsigned int)(cmin + lx);
    unsigned int cx1 = (unsigned int)(cmin + lx1);
    unsigned int cy0 = (unsigned int)(cmin + ly);
    unsigned int cy1 = (unsigned int)(cmin + ly1);
    unsigned int cz  = (unsigned int)(cmin + lz);
    float2 e00 = tab[hash3(cx0, cy0, cz)];
    float2 e10 = tab[hash3(cx1, cy0, cz)];
    float2 e01 = tab[hash3(cx0, cy1, cz)];
    float2 e11 = tab[hash3(cx1, cy1, cz)];
    HQuad q;
    q.c00 = __floats2half2_rn(e00.x * EMB_SCALE, e00.y * EMB_SCALE);
    q.c10 = __floats2half2_rn(e10.x * EMB_SCALE, e10.y * EMB_SCALE);
    q.c01 = __floats2half2_rn(e01.x * EMB_SCALE, e01.y * EMB_SCALE);
    q.c11 = __floats2half2_rn(e11.x * EMB_SCALE, e11.y * EMB_SCALE);
    return q;
}

__global__ void repack_smem(const float2* __restrict__ emb)
{
    int i = blockIdx.x * blockDim.x + threadIdx.x;
    if (i >= S_TOTAL) return;
    int l = 0;
    #pragma unroll
    for (int k = 0; k < N_SM - 1; ++k) if (i >= s_offc[k + 1]) l = k + 1;
    int idx = i - s_offc[l], d = s_dims[l];
    int lx = idx % d, t = idx / d, ly = t % d, lz = t / d;
    g_squad[i] = make_quad(emb + (size_t)l * TABLE_SIZE, s_cmin[l], d, lx, ly, lz);
}

__global__ void repack_gmem(const float2* __restrict__ emb)
{
    int i = blockIdx.x * blockDim.x + threadIdx.x;
    if (i >= G_TOTAL) return;
    int l = 0;
    #pragma unroll
    for (int k = 0; k < N_GD - 1; ++k) if (i >= g_offc[k + 1]) l = k + 1;
    int idx = i - g_offc[l], d = g_dims[l];
    int lx = idx % d, t = idx / d, ly = t % d, lz = t / d;
    g_gquad[i] = make_quad(emb + (size_t)(l + N_SM) * TABLE_SIZE,
                           g_cmin[l], d, lx, ly, lz);
}

// ---------------------------------------------------------------------------
// Per-point setup
// ---------------------------------------------------------------------------
struct Setup {
    float wx0, wx1, wy0, wy1, wz0, wz1;
    int   bx, by, bz;
    int   base;          // quad-array base index (valid if inWin)
    bool  inWin;
};

extern __shared__ HQuad s_quad[];

__device__ __forceinline__ Setup make_setup(const float* __restrict__ x,
                                            int point, float g, float rinv,
                                            int d, int cmin, int off)
{
    float px = __ldg(x + (size_t)point * 3 + 0);
    float py = __ldg(x + (size_t)point * 3 + 1);
    float pz = __ldg(x + (size_t)point * 3 + 2);
    px = fminf(fmaxf(px, -1.0f), 1.0f);
    py = fminf(fmaxf(py, -1.0f), 1.0f);
    pz = fminf(fmaxf(pz, -1.0f), 1.0f);

    float tx = __fsub_rn(px, -1.0f);
    float ty = __fsub_rn(py, -1.0f);
    float tz = __fsub_rn(pz, -1.0f);

    float blxf = floorf(__fmul_rn(tx, rinv));
    float blyf = floorf(__fmul_rn(ty, rinv));
    float blzf = floorf(__fmul_rn(tz, rinv));

    float vminx = __fadd_rn(__fmul_rn(blxf, g), -1.0f);
    float vminy = __fadd_rn(__fmul_rn(blyf, g), -1.0f);
    float vminz = __fadd_rn(__fmul_rn(blzf, g), -1.0f);

    float wx = __fmul_rn(__fsub_rn(px, vminx), rinv);
    float wy = __fmul_rn(__fsub_rn(py, vminy), rinv);
    float wz = __fmul_rn(__fsub_rn(pz, vminz), rinv);

    Setup s;
    s.bx = (int)blxf; s.by = (int)blyf; s.bz = (int)blzf;
    s.wx0 = 1.0f - wx; s.wx1 = wx;
    s.wy0 = 1.0f - wy; s.wy1 = wy;
    s.wz0 = 1.0f - wz; s.wz1 = wz;

    int lx = s.bx - cmin;
    int ly = s.by - cmin;
    int lz = s.bz - cmin;
    unsigned int lim = (unsigned int)(d - 1);        // d=1 for hash levels
    s.inWin = ((unsigned int)lx < lim) & ((unsigned int)ly < lim) &
              ((unsigned int)lz < lim);
    s.base = off + (lz * d + ly) * d + lx;
    return s;
}

__device__ __forceinline__ void hash_idx(const Setup& s, unsigned int* idx)
{
    unsigned int hx0 = (unsigned int)s.bx;
    unsigned int hx1 = hx0 + 1u;
    unsigned int hy0 = (unsigned int)s.by * PRIME_Y;
    unsigned int hy1 = hy0 + PRIME_Y;
    unsigned int hz0 = (unsigned int)s.bz * PRIME_Z;
    unsigned int hz1 = hz0 + PRIME_Z;
    unsigned int hyz[4] = {hy0 ^ hz0, hy0 ^ hz1, hy1 ^ hz0, hy1 ^ hz1};
    #pragma unroll
    for (int k = 0; k < 8; ++k) {
        unsigned int hx = (k & 4) ? hx1 : hx0;
        idx[k] = (hx ^ hyz[k & 3]) & HASH_MASK;
    }
}

__device__ __forceinline__ void accum_f2(const Setup& s, const float2* e,
                                         float& f0, float& f1)
{
    float wyz[4] = {s.wy0 * s.wz0, s.wy0 * s.wz1, s.wy1 * s.wz0, s.wy1 * s.wz1};
    #pragma unroll
    for (int k = 0; k < 8; ++k) {
        float cw = ((k & 4) ? s.wx1 : s.wx0) * wyz[k & 3];
        f0 += cw * e[k].x;
        f1 += cw * e[k].y;
    }
}

// Bilinear mix of one quad in (x,y).
__device__ __forceinline__ float2 quad_mix(const HQuad& q, const Setup& s)
{
    float2 a00 = __half22float2(q.c00);
    float2 a10 = __half22float2(q.c10);
    float2 a01 = __half22float2(q.c01);
    float2 a11 = __half22float2(q.c11);
    float2 r;
    r.x = s.wy0 * (s.wx0 * a00.x + s.wx1 * a10.x)
        + s.wy1 * (s.wx0 * a01.x + s.wx1 * a11.x);
    r.y = s.wy0 * (s.wx0 * a00.y + s.wx1 * a10.y)
        + s.wy1 * (s.wx0 * a01.y + s.wx1 * a11.y);
    return r;
}

__device__ __forceinline__ void quad_accum(const Setup& s,
                                           const HQuad& qz0, const HQuad& qz1,
                                           float& f0, float& f1)
{
    float2 t0 = quad_mix(qz0, s);
    float2 t1 = quad_mix(qz1, s);
    f0 += (s.wz0 * t0.x + s.wz1 * t1.x) * EMB_UNSCALE;
    f1 += (s.wz0 * t0.y + s.wz1 * t1.y) * EMB_UNSCALE;
}

__device__ __forceinline__ void gather_hash(const Setup& s,
                                            const float2* __restrict__ table,
                                            float& f0, float& f1)
{
    unsigned int idx[8];
    hash_idx(s, idx);
    float2 e[8];
    #pragma unroll
    for (int k = 0; k < 8; ++k) e[k] = __ldg(table + idx[k]);
    accum_f2(s, e, f0, f1);
}

// ---------------------------------------------------------------------------
// Main encoder: persistent 1024-thread blocks; 2 points per thread.
// tid&15 = level -> per-warp output stores contiguous; the path class is
// uniform across a thread's two points (same level).
// ---------------------------------------------------------------------------
__global__ __launch_bounds__(1024, 1)
void ingp_hash_encode_kernel(const float*  __restrict__ x,
                             const float2* __restrict__ emb,
                             float2*       __restrict__ out,
                             int n, LevelParams P)
{
    for (int i = threadIdx.x; i < S_TOTAL; i += blockDim.x)
        s_quad[i] = g_squad[i];
    __syncthreads();

    const int level    = threadIdx.x & (N_LEVELS - 1);
    const int local_pt = threadIdx.x >> 4;           // 0..63
    const float g    = P.g[level];
    const float rinv = P.rinv[level];

    int cls, d = 1, cmin = 0, off = 0;
    if (level < N_SM) {
        cls = 0; d = s_dims[level]; cmin = s_cmin[level]; off = s_offc[level];
    } else if (level < N_SM + N_GD) {
        cls = 1;
        int j = level - N_SM;
        d = g_dims[j]; cmin = g_cmin[j]; off = g_offc[j];
    } else {
        cls = 2;
    }
    const int zstride = d * d;
    const float2* __restrict__ table = emb + (size_t)level * TABLE_SIZE;

    const int pts_per_blk = 128;
    const int nchunks = (n + pts_per_blk - 1) / pts_per_blk;

    for (int c = blockIdx.x; c < nchunks; c += gridDim.x) {
        int p0 = c * pts_per_blk + local_pt;
        int p1 = p0 + 64;
        bool v0 = p0 < n, v1 = p1 < n;
        int q0 = v0 ? p0 : 0;
        int q1 = v1 ? p1 : 0;

        Setup sA = make_setup(x, q0, g, rinv, d, cmin, off);
        Setup sB = make_setup(x, q1, g, rinv, d, cmin, off);

        float a0 = 0.0f, a1 = 0.0f, b0 = 0.0f, b1 = 0.0f;

        if (cls == 2) {
            // hash levels 12-15: 16 independent 8B loads batched
            unsigned int ia[8], ib[8];
            hash_idx(sA, ia);
            hash_idx(sB, ib);
            float2 ea[8], eb[8];
            #pragma unroll
            for (int k = 0; k < 8; ++k) ea[k] = __ldg(table + ia[k]);
            #pragma unroll
            for (int k = 0; k < 8; ++k) eb[k] = __ldg(table + ib[k]);
            accum_f2(sA, ea, a0, a1);
            accum_f2(sB, eb, b0, b1);
        } else if (cls == 1) {
            // dense gmem quads, levels 4-11: 4 x LDG.128 batched
            if (sA.inWin & sB.inWin) {
                HQuad qa0 = g_gquad[sA.base];
                HQuad qa1 = g_gquad[sA.base + zstride];
                HQuad qb0 = g_gquad[sB.base];
                HQuad qb1 = g_gquad[sB.base + zstride];
                quad_accum(sA, qa0, qa1, a0, a1);
                quad_accum(sB, qb0, qb1, b0, b1);
            } else {
                if (sA.inWin) {
                    HQuad q0_ = g_gquad[sA.base];
                    HQuad q1_ = g_gquad[sA.base + zstride];
                    quad_accum(sA, q0_, q1_, a0, a1);
                } else gather_hash(sA, table, a0, a1);
                if (sB.inWin) {
                    HQuad q0_ = g_gquad[sB.base];
                    HQuad q1_ = g_gquad[sB.base + zstride];
                    quad_accum(sB, q0_, q1_, b0, b1);
                } else gather_hash(sB, table, b0, b1);
            }
        } else {
            // smem quads, levels 0-3: 4 x LDS.128
            if (sA.inWin & sB.inWin) {
                HQuad qa0 = s_quad[sA.base];
                HQuad qa1 = s_quad[sA.base + zstride];
                HQuad qb0 = s_quad[sB.base];
                HQuad qb1 = s_quad[sB.base + zstride];
                quad_accum(sA, qa0, qa1, a0, a1);
                quad_accum(sB, qb0, qb1, b0, b1);
            } else {
                if (sA.inWin) {
                    HQuad q0_ = s_quad[sA.base];
                    HQuad q1_ = s_quad[sA.base + zstride];
                    quad_accum(sA, q0_, q1_, a0, a1);
                } else gather_hash(sA, table, a0, a1);
                if (sB.inWin) {
                    HQuad q0_ = s_quad[sB.base];
                    HQuad q1_ = s_quad[sB.base + zstride];
                    quad_accum(sB, q0_, q1_, b0, b1);
                } else gather_hash(sB, table, b0, b1);
            }
        }

        if (v0) out[(size_t)p0 * N_LEVELS + level] = make_float2(a0, a1);
        if (v1) out[(size_t)p1 * N_LEVELS + level] = make_float2(b0, b1);
    }
}

extern "C" void kernel_launch(void* const* d_in, const int* in_sizes, int n_in,
                              void* d_out, int out_size)
{
    const float* x   = (const float*)d_in[0];
    const float* emb = (const float*)d_in[1];
    int n = in_sizes[0] / 3;

    LevelParams P;
    double b = exp((log(512.0) - log(16.0)) / 15.0);
    for (int l = 0; l < N_LEVELS; ++l) {
        float res = (float)floor(16.0 * pow(b, (double)l));
        P.g[l]    = 2.0f / res;
        P.rinv[l] = (float)(1.0 / (double)P.g[l]);
    }

    size_t smem_bytes = (size_t)S_TOTAL * sizeof(HQuad);   // ~186.5 KB
    cudaFuncSetAttribute(ingp_hash_encode_kernel,
                         cudaFuncAttributeMaxDynamicSharedMemorySize,
                         (int)smem_bytes);

    int num_sms = 148;
    cudaDeviceGetAttribute(&num_sms, cudaDevAttrMultiProcessorCount, 0);

    repack_smem<<<(S_TOTAL + 255) / 256, 256>>>((const float2*)emb);
    repack_gmem<<<(G_TOTAL + 255) / 256, 256>>>((const float2*)emb);

    ingp_hash_encode_kernel<<<num_sms, 1024, smem_bytes>>>(
        x, (const float2*)emb, (float2*)d_out, n, P);
}

// round 13
// speedup vs baseline: 1.4290x; 1.4290x over previous
#include <cuda_runtime.h>
#include <cuda_fp16.h>
#include <math.h>

#define N_LEVELS   16
#define LOG2_T     19
#define TABLE_SIZE (1 << LOG2_T)
#define HASH_MASK  (TABLE_SIZE - 1)

#define PRIME_Y 2654435761u
#define PRIME_Z 805459861u

#define EMB_SCALE   8192.0f
#define EMB_UNSCALE (1.0f / 8192.0f)

// 8B pair: both x-corners (fp16x2 each) — smem levels 0-4.
struct __align__(8)  HPair { __half2 a, b; };
// 16B quad: (x,y) 2x2 corners at one z (fp16x2 each) — gmem levels 5-11.
struct __align__(16) HQuad { __half2 c00, c10, c01, c11; };

// ---- smem levels 0-4 (pairs), identical to the 291.9us config
#define N_SM 5
__device__ __constant__ int s_dims[N_SM] = {10, 12, 15, 18, 22};
__device__ __constant__ int s_cmin[N_SM] = { 8, 10, 12, 16, 20};
__device__ __constant__ int s_offc[N_SM] = {0, 1000, 2728, 6103, 11935};
#define S_TOTAL 22583

// ---- gmem dense levels 5-11 (quads), +-1 margin windows
#define N_GD 7
__device__ __constant__ int g_dims[N_GD] = {28, 36, 44, 55, 68, 84, 106};
__device__ __constant__ int g_cmin[N_GD] = {24, 30, 39, 49, 62, 79, 100};
__device__ __constant__ int g_offc[N_GD] =
    {0, 21952, 68608, 153792, 320167, 634599, 1227303};
#define G_TOTAL 2418319

__device__ HPair  g_spair[S_TOTAL];
__device__ float2 g_cell [G_TOTAL];   // stage-1 temp: dense single cells
__device__ HQuad  g_gquad[G_TOTAL];   // stage-2 output: quads

struct LevelParams {
    float g[N_LEVELS];
    float rinv[N_LEVELS];
};

__device__ __forceinline__ unsigned int hash3(unsigned int cx, unsigned int cy,
                                              unsigned int cz)
{
    return (cx ^ (cy * PRIME_Y) ^ (cz * PRIME_Z)) & HASH_MASK;
}

// ---------------------------------------------------------------------------
// Repack kernels
// ---------------------------------------------------------------------------
__global__ void repack_smem(const float2* __restrict__ emb)
{
    int i = blockIdx.x * blockDim.x + threadIdx.x;
    if (i >= S_TOTAL) return;
    int l = 0;
    #pragma unroll
    for (int k = 0; k < N_SM - 1; ++k) if (i >= s_offc[k + 1]) l = k + 1;
    int idx = i - s_offc[l], d = s_dims[l];
    int lx = idx % d;
    int t  = idx / d;
    int ly = t % d;
    int lz = t / d;
    int lx1 = min(lx + 1, d - 1);

    unsigned int cy = (unsigned int)(s_cmin[l] + ly);
    unsigned int cz = (unsigned int)(s_cmin[l] + lz);
    float2 c0 = emb[(size_t)l * TABLE_SIZE + hash3((unsigned int)(s_cmin[l] + lx),  cy, cz)];
    float2 c1 = emb[(size_t)l * TABLE_SIZE + hash3((unsigned int)(s_cmin[l] + lx1), cy, cz)];

    HPair p;
    p.a = __floats2half2_rn(c0.x * EMB_SCALE, c0.y * EMB_SCALE);
    p.b = __floats2half2_rn(c1.x * EMB_SCALE, c1.y * EMB_SCALE);
    g_spair[i] = p;
}

// Stage 1: ONE random gather per dense cell (no duplication).
__global__ void repack_cell(const float2* __restrict__ emb)
{
    int i = blockIdx.x * blockDim.x + threadIdx.x;
    if (i >= G_TOTAL) return;
    int l = 0;
    #pragma unroll
    for (int k = 0; k < N_GD - 1; ++k) if (i >= g_offc[k + 1]) l = k + 1;
    int idx = i - g_offc[l], d = g_dims[l];
    int lx = idx % d;
    int t  = idx / d;
    int ly = t % d;
    int lz = t / d;
    g_cell[i] = emb[(size_t)(l + N_SM) * TABLE_SIZE +
                    hash3((unsigned int)(g_cmin[l] + lx),
                          (unsigned int)(g_cmin[l] + ly),
                          (unsigned int)(g_cmin[l] + lz))];
}

// Stage 2: assemble quads from the dense temp via unit-stride L2-hot reads.
__global__ void repack_quad()
{
    int i = blockIdx.x * blockDim.x + threadIdx.x;
    if (i >= G_TOTAL) return;
    int l = 0;
    #pragma unroll
    for (int k = 0; k < N_GD - 1; ++k) if (i >= g_offc[k + 1]) l = k + 1;
    int idx = i - g_offc[l], d = g_dims[l];
    int lx = idx % d;
    int t  = idx / d;
    int ly = t % d;
    int dx = (lx + 1 < d) ? 1 : 0;        // clamped entries never consumed
    int dy = (ly + 1 < d) ? d : 0;

    float2 c00 = g_cell[i];
    float2 c10 = g_cell[i + dx];
    float2 c01 = g_cell[i + dy];
    float2 c11 = g_cell[i + dy + dx];

    HQuad q;
    q.c00 = __floats2half2_rn(c00.x * EMB_SCALE, c00.y * EMB_SCALE);
    q.c10 = __floats2half2_rn(c10.x * EMB_SCALE, c10.y * EMB_SCALE);
    q.c01 = __floats2half2_rn(c01.x * EMB_SCALE, c01.y * EMB_SCALE);
    q.c11 = __floats2half2_rn(c11.x * EMB_SCALE, c11.y * EMB_SCALE);
    g_gquad[i] = q;
}

// ---------------------------------------------------------------------------
// Per-point setup
// ---------------------------------------------------------------------------
struct Setup {
    float wx0, wx1, wy0, wy1, wz0, wz1;
    int   bx, by, bz;
    int   base;          // dense-array base index (valid if inWin)
    bool  inWin;
};

extern __shared__ HPair s_pair[];

__device__ __forceinline__ Setup make_setup(const float* __restrict__ x,
                                            int point, float g, float rinv,
                                            int d, int cmin, int off)
{
    float px = __ldg(x + (size_t)point * 3 + 0);
    float py = __ldg(x + (size_t)point * 3 + 1);
    float pz = __ldg(x + (size_t)point * 3 + 2);
    px = fminf(fmaxf(px, -1.0f), 1.0f);
    py = fminf(fmaxf(py, -1.0f), 1.0f);
    pz = fminf(fmaxf(pz, -1.0f), 1.0f);

    float tx = __fsub_rn(px, -1.0f);
    float ty = __fsub_rn(py, -1.0f);
    float tz = __fsub_rn(pz, -1.0f);

    float blxf = floorf(__fmul_rn(tx, rinv));
    float blyf = floorf(__fmul_rn(ty, rinv));
    float blzf = floorf(__fmul_rn(tz, rinv));

    float vminx = __fadd_rn(__fmul_rn(blxf, g), -1.0f);
    float vminy = __fadd_rn(__fmul_rn(blyf, g), -1.0f);
    float vminz = __fadd_rn(__fmul_rn(blzf, g), -1.0f);

    float wx = __fmul_rn(__fsub_rn(px, vminx), rinv);
    float wy = __fmul_rn(__fsub_rn(py, vminy), rinv);
    float wz = __fmul_rn(__fsub_rn(pz, vminz), rinv);

    Setup s;
    s.bx = (int)blxf; s.by = (int)blyf; s.bz = (int)blzf;
    s.wx0 = 1.0f - wx; s.wx1 = wx;
    s.wy0 = 1.0f - wy; s.wy1 = wy;
    s.wz0 = 1.0f - wz; s.wz1 = wz;

    int lx = s.bx - cmin;
    int ly = s.by - cmin;
    int lz = s.bz - cmin;
    unsigned int lim = (unsigned int)(d - 1);        // d=1 for hash levels
    s.inWin = ((unsigned int)lx < lim) & ((unsigned int)ly < lim) &
              ((unsigned int)lz < lim);
    s.base = off + (lz * d + ly) * d + lx;
    return s;
}

__device__ __forceinline__ void hash_idx(const Setup& s, unsigned int* idx)
{
    unsigned int hx0 = (unsigned int)s.bx;
    unsigned int hx1 = hx0 + 1u;
    unsigned int hy0 = (unsigned int)s.by * PRIME_Y;
    unsigned int hy1 = hy0 + PRIME_Y;
    unsigned int hz0 = (unsigned int)s.bz * PRIME_Z;
    unsigned int hz1 = hz0 + PRIME_Z;
    unsigned int hyz[4] = {hy0 ^ hz0, hy0 ^ hz1, hy1 ^ hz0, hy1 ^ hz1};
    #pragma unroll
    for (int k = 0; k < 8; ++k) {
        unsigned int hx = (k & 4) ? hx1 : hx0;
        idx[k] = (hx ^ hyz[k & 3]) & HASH_MASK;
    }
}

__device__ __forceinline__ void accum_f2(const Setup& s, const float2* e,
                                         float& f0, float& f1)
{
    float wyz[4] = {s.wy0 * s.wz0, s.wy0 * s.wz1, s.wy1 * s.wz0, s.wy1 * s.wz1};
    #pragma unroll
    for (int k = 0; k < 8; ++k) {
        float cw = ((k & 4) ? s.wx1 : s.wx0) * wyz[k & 3];
        f0 += cw * e[k].x;
        f1 += cw * e[k].y;
    }
}

// smem pair path (levels 0-4): 4 x LDS.64, accumulate, unscale.
__device__ __forceinline__ void pair_accum(const Setup& s, const HPair* p,
                                           float& f0, float& f1)
{
    float wyz[4] = {s.wy0 * s.wz0, s.wy0 * s.wz1, s.wy1 * s.wz0, s.wy1 * s.wz1};
    float t0 = 0.0f, t1 = 0.0f;
    #pragma unroll
    for (int k = 0; k < 4; ++k) {
        float2 a = __half22float2(p[k].a);
        float2 b = __half22float2(p[k].b);
        float w = wyz[k];
        t0 += w * (s.wx0 * a.x + s.wx1 * b.x);
        t1 += w * (s.wx0 * a.y + s.wx1 * b.y);
    }
    f0 += t0 * EMB_UNSCALE;
    f1 += t1 * EMB_UNSCALE;
}

// gmem quad path (levels 5-11): bilinear (x,y) per z-slab, lerp z, unscale.
__device__ __forceinline__ float2 quad_mix(const HQuad& q, const Setup& s)
{
    float2 a00 = __half22float2(q.c00);
    float2 a10 = __half22float2(q.c10);
    float2 a01 = __half22float2(q.c01);
    float2 a11 = __half22float2(q.c11);
    float2 r;
    r.x = s.wy0 * (s.wx0 * a00.x + s.wx1 * a10.x)
        + s.wy1 * (s.wx0 * a01.x + s.wx1 * a11.x);
    r.y = s.wy0 * (s.wx0 * a00.y + s.wx1 * a10.y)
        + s.wy1 * (s.wx0 * a01.y + s.wx1 * a11.y);
    return r;
}

__device__ __forceinline__ void quad_accum(const Setup& s,
                                           const HQuad& qz0, const HQuad& qz1,
                                           float& f0, float& f1)
{
    float2 t0 = quad_mix(qz0, s);
    float2 t1 = quad_mix(qz1, s);
    f0 += (s.wz0 * t0.x + s.wz1 * t1.x) * EMB_UNSCALE;
    f1 += (s.wz0 * t0.y + s.wz1 * t1.y) * EMB_UNSCALE;
}

__device__ __forceinline__ void gather_hash(const Setup& s,
                                            const float2* __restrict__ table,
                                            float& f0, float& f1)
{
    unsigned int idx[8];
    hash_idx(s, idx);
    float2 e[8];
    #pragma unroll
    for (int k = 0; k < 8; ++k) e[k] = __ldg(table + idx[k]);
    accum_f2(s, e, f0, f1);
}

__device__ __forceinline__ void gather_spair(const Setup& s, int sy, int sz,
                                             float& f0, float& f1)
{
    HPair p[4];
    #pragma unroll
    for (int k = 0; k < 4; ++k)
        p[k] = s_pair[s.base + (k >> 1) * sy + (k & 1) * sz];
    pair_accum(s, p, f0, f1);
}

// ---------------------------------------------------------------------------
// Main encoder: persistent 1024-thread blocks; 2 points per thread.
// tid&15 = level -> contiguous per-warp output stores; path class uniform
// across a thread's two points (same level).
// ---------------------------------------------------------------------------
__global__ __launch_bounds__(1024, 1)
void ingp_hash_encode_kernel(const float*  __restrict__ x,
                             const float2* __restrict__ emb,
                             float2*       __restrict__ out,
                             int n, LevelParams P)
{
    for (int i = threadIdx.x; i < S_TOTAL; i += blockDim.x)
        s_pair[i] = g_spair[i];
    __syncthreads();

    const int level    = threadIdx.x & (N_LEVELS - 1);
    const int local_pt = threadIdx.x >> 4;           // 0..63
    const float g    = P.g[level];
    const float rinv = P.rinv[level];

    int cls, d = 1, cmin = 0, off = 0;
    if (level < N_SM) {
        cls = 0; d = s_dims[level]; cmin = s_cmin[level]; off = s_offc[level];
    } else if (level < N_SM + N_GD) {
        cls = 1;
        int j = level - N_SM;
        d = g_dims[j]; cmin = g_cmin[j]; off = g_offc[j];
    } else {
        cls = 2;
    }
    const int sy = d, sz = d * d;
    const float2* __restrict__ table = emb + (size_t)level * TABLE_SIZE;

    const int pts_per_blk = 128;
    const int nchunks = (n + pts_per_blk - 1) / pts_per_blk;

    for (int c = blockIdx.x; c < nchunks; c += gridDim.x) {
        int p0 = c * pts_per_blk + local_pt;
        int p1 = p0 + 64;
        bool v0 = p0 < n, v1 = p1 < n;
        int q0 = v0 ? p0 : 0;
        int q1 = v1 ? p1 : 0;

        Setup sA = make_setup(x, q0, g, rinv, d, cmin, off);
        Setup sB = make_setup(x, q1, g, rinv, d, cmin, off);

        float a0 = 0.0f, a1 = 0.0f, b0 = 0.0f, b1 = 0.0f;

        if (cls == 2) {
            // hash levels 12-15: 16 independent 8B loads batched
            unsigned int ia[8], ib[8];
            hash_idx(sA, ia);
            hash_idx(sB, ib);
            float2 ea[8], eb[8];
            #pragma unroll
            for (int k = 0; k < 8; ++k) ea[k] = __ldg(table + ia[k]);
            #pragma unroll
            for (int k = 0; k < 8; ++k) eb[k] = __ldg(table + ib[k]);
            accum_f2(sA, ea, a0, a1);
            accum_f2(sB, eb, b0, b1);
        } else if (cls == 1) {
            // dense gmem quads, levels 5-11: 4 x LDG.128 batched (2 per point)
            if (sA.inWin & sB.inWin) {
                HQuad qa0 = g_gquad[sA.base];
                HQuad qa1 = g_gquad[sA.base + sz];
                HQuad qb0 = g_gquad[sB.base];
                HQuad qb1 = g_gquad[sB.base + sz];
                quad_accum(sA, qa0, qa1, a0, a1);
                quad_accum(sB, qb0, qb1, b0, b1);
            } else {
                if (sA.inWin) {
                    HQuad u0 = g_gquad[sA.base];
                    HQuad u1 = g_gquad[sA.base + sz];
                    quad_accum(sA, u0, u1, a0, a1);
                } else gather_hash(sA, table, a0, a1);
                if (sB.inWin) {
                    HQuad u0 = g_gquad[sB.base];
                    HQuad u1 = g_gquad[sB.base + sz];
                    quad_accum(sB, u0, u1, b0, b1);
                } else gather_hash(sB, table, b0, b1);
            }
        } else {
            // smem pairs, levels 0-4
            if (sA.inWin & sB.inWin) {
                gather_spair(sA, sy, sz, a0, a1);
                gather_spair(sB, sy, sz, b0, b1);
            } else {
                if (sA.inWin) gather_spair(sA, sy, sz, a0, a1);
                else          gather_hash (sA, table, a0, a1);
                if (sB.inWin) gather_spair(sB, sy, sz, b0, b1);
                else          gather_hash (sB, table, b0, b1);
            }
        }

        if (v0) out[(size_t)p0 * N_LEVELS + level] = make_float2(a0, a1);
        if (v1) out[(size_t)p1 * N_LEVELS + level] = make_float2(b0, b1);
    }
}

extern "C" void kernel_launch(void* const* d_in, const int* in_sizes, int n_in,
                              void* d_out, int out_size)
{
    const float* x   = (const float*)d_in[0];
    const float* emb = (const float*)d_in[1];
    int n = in_sizes[0] / 3;

    LevelParams P;
    double b = exp((log(512.0) - log(16.0)) / 15.0);
    for (int l = 0; l < N_LEVELS; ++l) {
        float res = (float)floor(16.0 * pow(b, (double)l));
        P.g[l]    = 2.0f / res;
        P.rinv[l] = (float)(1.0 / (double)P.g[l]);
    }

    size_t smem_bytes = (size_t)S_TOTAL * sizeof(HPair);   // ~180.7 KB
    cudaFuncSetAttribute(ingp_hash_encode_kernel,
                         cudaFuncAttributeMaxDynamicSharedMemorySize,
                         (int)smem_bytes);

    int num_sms = 148;
    cudaDeviceGetAttribute(&num_sms, cudaDevAttrMultiProcessorCount, 0);

    repack_smem<<<(S_TOTAL + 255) / 256, 256>>>((const float2*)emb);
    repack_cell<<<(G_TOTAL + 255) / 256, 256>>>((const float2*)emb);
    repack_quad<<<(G_TOTAL + 255) / 256, 256>>>();

    ingp_hash_encode_kernel<<<num_sms, 1024, smem_bytes>>>(
        x, (const float2*)emb, (float2*)d_out, n, P);
}